// round 12
// baseline (speedup 1.0000x reference)
#include <cuda_runtime.h>
#include <cuda_fp16.h>
#include <mma.h>

using namespace nvcuda;

#define NN 50000
#define NE 800000
#define NG 1024
#define DIN 9
#define DD 64
#define SCAN_BLKS ((NN + 255) / 256)   // 196
#define GMN 64                          // nodes per gemm64 block
#define EPAD (NE + 16*NN)               // padded edge array size (rows padded to x16)

// ---- scratch (static device globals) ----
__device__ __half2  g_h2 [NN*32];        // activations (post-tanh), fp16
__device__ __half2  g_z2 [(NN+1)*32];    // z = dinv * (h @ W), fp16; row NN = 0
__device__ float    g_zx [(NN+1)*16];    // dinv * x, padded to 16; row NN = 0
__device__ float    g_aggx[NN*DIN];      // layer-0 aggregate
__device__ int      g_degi[NN];          // in-degree (no self loop)
__device__ float    g_dinv[NN];
__device__ int      g_rp  [NN];          // padded CSR row start (16-aligned)
__device__ int      g_cur [NN];          // fill cursor (pre-seeded with rp)
__device__ int      g_es  [EPAD];        // src indices; pre-filled with NN (dummy)
__device__ int      g_bsum[256];
__device__ unsigned g_gmax[NG*DD];
__device__ float    g_gsum[NG*DD];
__device__ float    g_gcnt[NG];

__device__ __forceinline__ unsigned fkey(float f) {
    unsigned b = __float_as_uint(f);
    return (b & 0x80000000u) ? ~b : (b | 0x80000000u);
}
__device__ __forceinline__ float funkey(unsigned k) {
    unsigned b = (k & 0x80000000u) ? (k & 0x7FFFFFFFu) : ~k;
    return __uint_as_float(b);
}

// init: zero counters/pools AND blanket-fill es with dummy node (covers pads)
__global__ void k_init() {
    int i = blockIdx.x * blockDim.x + threadIdx.x;
    if (i < EPAD/4) reinterpret_cast<int4*>(g_es)[i] = make_int4(NN, NN, NN, NN);
    if (i < NN) g_degi[i] = 0;
    if (i < NG*DD) { g_gmax[i] = 0u; g_gsum[i] = 0.0f; }
    if (i < NG) g_gcnt[i] = 0.0f;
    if (i < 32) g_z2[NN*32 + i] = __float2half2_rn(0.0f);   // dummy z row
    if (i < 16) g_zx[NN*16 + i] = 0.0f;                     // dummy zx row
}

__global__ void k_deg(const int4* __restrict__ dst4) {
    int e = blockIdx.x * blockDim.x + threadIdx.x;
    if (e >= NE/4) return;
    int4 d = dst4[e];
    atomicAdd(&g_degi[d.x], 1);
    atomicAdd(&g_degi[d.y], 1);
    atomicAdd(&g_degi[d.z], 1);
    atomicAdd(&g_degi[d.w], 1);
}

// shuffle scan of degree PADDED TO x16 -> rp (exclusive), block sums
__global__ void k_scan1() {
    __shared__ int wsum[8], wpre[8];
    int t = threadIdx.x, i = blockIdx.x * 256 + t;
    int lane = t & 31, w = t >> 5;
    int v = (i < NN) ? ((g_degi[i] + 15) & ~15) : 0;
    int s = v;
    #pragma unroll
    for (int off = 1; off < 32; off <<= 1) {
        int u = __shfl_up_sync(0xFFFFFFFFu, s, off);
        if (lane >= off) s += u;
    }
    if (lane == 31) wsum[w] = s;
    __syncthreads();
    if (t == 0) {
        int a = 0;
        #pragma unroll
        for (int j = 0; j < 8; j++) { wpre[j] = a; a += wsum[j]; }
    }
    __syncthreads();
    int incl = s + wpre[w];
    if (i < NN) g_rp[i] = incl - v;
    if (t == 255) g_bsum[blockIdx.x] = incl;
}

// re-scan bsum + apply; cursor=rp, dinv (pads pre-filled by k_init)
__global__ void k_scan3() {
    __shared__ int wsum[8], wpre[8], allincl[256];
    int t = threadIdx.x;
    int lane = t & 31, w = t >> 5;
    int v = (t < SCAN_BLKS) ? g_bsum[t] : 0;
    int s = v;
    #pragma unroll
    for (int off = 1; off < 32; off <<= 1) {
        int u = __shfl_up_sync(0xFFFFFFFFu, s, off);
        if (lane >= off) s += u;
    }
    if (lane == 31) wsum[w] = s;
    __syncthreads();
    if (t == 0) {
        int a = 0;
        #pragma unroll
        for (int j = 0; j < 8; j++) { wpre[j] = a; a += wsum[j]; }
    }
    __syncthreads();
    allincl[t] = s + wpre[w];
    __syncthreads();
    int boff = (blockIdx.x > 0) ? allincl[blockIdx.x - 1] : 0;
    int i = blockIdx.x * 256 + t;
    if (i < NN) {
        int rp = g_rp[i] + boff;
        g_rp[i] = rp;
        g_cur[i] = rp;
        g_dinv[i] = rsqrtf(1.0f + (float)g_degi[i]);
    }
}

// coalesced zx = dinv * x (padded to 16 floats/row)
__global__ void k_zx(const float* __restrict__ x) {
    int t = blockIdx.x * blockDim.x + threadIdx.x;
    if (t >= NN*16) return;
    int n = t >> 4, k = t & 15;
    float v = (k < DIN) ? g_dinv[n] * x[n*DIN + k] : 0.0f;
    g_zx[t] = v;
}

// 2 int4s per thread: 8 independent atomic->store chains; cur pre-seeded with rp
__global__ void k_fill(const int4* __restrict__ src4, const int4* __restrict__ dst4) {
    int e = blockIdx.x * blockDim.x + threadIdx.x;
    if (e >= NE/8) return;
    int4 s0 = src4[2*e], d0 = dst4[2*e];
    int4 s1 = src4[2*e+1], d1 = dst4[2*e+1];
    g_es[atomicAdd(&g_cur[d0.x], 1)] = s0.x;
    g_es[atomicAdd(&g_cur[d0.y], 1)] = s0.y;
    g_es[atomicAdd(&g_cur[d0.z], 1)] = s0.z;
    g_es[atomicAdd(&g_cur[d0.w], 1)] = s0.w;
    g_es[atomicAdd(&g_cur[d1.x], 1)] = s1.x;
    g_es[atomicAdd(&g_cur[d1.y], 1)] = s1.y;
    g_es[atomicAdd(&g_cur[d1.z], 1)] = s1.z;
    g_es[atomicAdd(&g_cur[d1.w], 1)] = s1.w;
}

// layer-0: aggx[d] = dinv[d] * (zx[d] + sum zx[s]); 16 lanes/node
__global__ void k_gather9() {
    int t = blockIdx.x * blockDim.x + threadIdx.x;
    int n = t >> 4, c = t & 15;
    if (n >= NN) return;
    int rp = g_rp[n];
    int quads = (g_degi[n] + 3) >> 2;     // partial quads hold dummy NN -> zx=0
    float a0 = g_zx[n*16 + c], a1 = 0.0f;
    const int4* sp = reinterpret_cast<const int4*>(&g_es[rp]);
    int it = 0;
    for (; it + 2 <= quads; it += 2) {
        int4 s0 = sp[it], s1 = sp[it + 1];
        a0 += g_zx[s0.x*16 + c];
        a1 += g_zx[s0.y*16 + c];
        a0 += g_zx[s0.z*16 + c];
        a1 += g_zx[s0.w*16 + c];
        a0 += g_zx[s1.x*16 + c];
        a1 += g_zx[s1.y*16 + c];
        a0 += g_zx[s1.z*16 + c];
        a1 += g_zx[s1.w*16 + c];
    }
    if (it < quads) {
        int4 s0 = sp[it];
        a0 += g_zx[s0.x*16 + c];
        a1 += g_zx[s0.y*16 + c];
        a0 += g_zx[s0.z*16 + c];
        a1 += g_zx[s0.w*16 + c];
    }
    if (c < DIN) g_aggx[n*DIN + c] = g_dinv[n] * (a0 + a1);
}

// h0 = tanh(aggx @ W0 + b0) -> fp16; 8 nodes/block, lane computes 2 cols
__global__ void k_gemm0f(const float* __restrict__ W, const float* __restrict__ b) {
    __shared__ float Ws[DIN*DD];
    __shared__ float axs[8][DIN];
    int tid = threadIdx.x;
    for (int i = tid; i < DIN*DD; i += 256) Ws[i] = W[i];
    int nb = blockIdx.x * 8;
    if (tid < 8*DIN) {
        int r = tid / DIN, k = tid % DIN, n = nb + r;
        axs[r][k] = (n < NN) ? g_aggx[n*DIN + k] : 0.0f;
    }
    __syncthreads();
    int r = tid >> 5, l = tid & 31;
    int n = nb + r;
    if (n >= NN) return;
    int c0 = 2*l, c1 = 2*l + 1;
    float s0 = b[c0], s1 = b[c1];
    #pragma unroll
    for (int k = 0; k < DIN; k++) {
        float a = axs[r][k];
        s0 += a * Ws[k*DD + c0];
        s1 += a * Ws[k*DD + c1];
    }
    g_h2[n*32 + l] = __floats2half2_rn(tanhf(s0), tanhf(s1));
}

// z = dinv * (h @ W) via tensor cores: fp16 in, fp32 acc, fp16 out.
#define HP 72
__global__ void k_gemm64(const float* __restrict__ W) {
    __shared__ __half Hs [GMN][HP];
    __shared__ __half Wsh[DD ][HP];
    __shared__ float  stage[8][16][20];
    int tid = threadIdx.x;
    int wid = tid >> 5, lane = tid & 31;
    int nb = blockIdx.x * GMN;

    #pragma unroll
    for (int i = 0; i < 4; i++) {
        int idx = tid + i*256;
        float4 f = reinterpret_cast<const float4*>(W)[idx];
        int r = idx >> 4, c0 = (idx & 15) * 4;
        __half2 p0 = __floats2half2_rn(f.x, f.y);
        __half2 p1 = __floats2half2_rn(f.z, f.w);
        *reinterpret_cast<__half2*>(&Wsh[r][c0])     = p0;
        *reinterpret_cast<__half2*>(&Wsh[r][c0 + 2]) = p1;
    }
    #pragma unroll
    for (int i = 0; i < 2; i++) {
        int idx = tid + i*256;
        int n = idx >> 3, q = idx & 7;
        int gn = nb + n;
        uint4 v = make_uint4(0u, 0u, 0u, 0u);
        if (gn < NN) v = reinterpret_cast<const uint4*>(g_h2)[gn*8 + q];
        *reinterpret_cast<uint4*>(&Hs[n][q*8]) = v;
    }
    __syncthreads();

    wmma::fragment<wmma::matrix_a, 16, 16, 16, __half, wmma::row_major> fa;
    wmma::fragment<wmma::matrix_b, 16, 16, 16, __half, wmma::row_major> fb;

    #pragma unroll
    for (int tt = 0; tt < 2; tt++) {
        int t = wid + tt*8;
        int tr = t >> 2, tc = t & 3;
        wmma::fragment<wmma::accumulator, 16, 16, 16, float> fc;
        wmma::fill_fragment(fc, 0.0f);
        #pragma unroll
        for (int k0 = 0; k0 < 4; k0++) {
            wmma::load_matrix_sync(fa, &Hs[tr*16][k0*16], HP);
            wmma::load_matrix_sync(fb, &Wsh[k0*16][tc*16], HP);
            wmma::mma_sync(fc, fa, fb, fc);
        }
        wmma::store_matrix_sync(&stage[wid][0][0], fc, 20, wmma::mem_row_major);
        __syncwarp();
        #pragma unroll
        for (int e = 0; e < 4; e++) {
            int idx = lane + e*32;
            int r = idx >> 3, c2 = idx & 7;
            int gn = nb + tr*16 + r;
            if (gn < NN) {
                float dv = g_dinv[gn];
                float f0 = stage[wid][r][c2*2];
                float f1 = stage[wid][r][c2*2 + 1];
                g_z2[gn*32 + tc*8 + c2] = __floats2half2_rn(dv*f0, dv*f1);
            }
        }
        __syncwarp();
    }
}

__device__ __forceinline__ void quad_acc(int4 q, int lane, float& ax, float& ay) {
    __half2 h0 = g_z2[q.x*32 + lane];
    __half2 h1 = g_z2[q.y*32 + lane];
    __half2 h2 = g_z2[q.z*32 + lane];
    __half2 h3 = g_z2[q.w*32 + lane];
    __half2 sA = __hadd2(__hadd2(h0, h1), __hadd2(h2, h3));
    float2 fA = __half22float2(sA);
    ax += fA.x;
    ay += fA.y;
}

// gather: warp-per-node, tail-free 16-edge chunks (16 row loads in flight)
template <bool POOL>
__global__ void k_gather64(const float* __restrict__ b, const int* __restrict__ batch) {
    int n = (blockIdx.x * blockDim.x + threadIdx.x) >> 5;
    int lane = threadIdx.x & 31;
    if (n >= NN) return;
    int rp = g_rp[n];
    int chunks = (g_degi[n] + 15) >> 4;   // rows padded to x16 with dummy NN
    float2 self = __half22float2(g_z2[n*32 + lane]);
    float ax0 = self.x, ay0 = self.y;
    float ax1 = 0.0f,   ay1 = 0.0f;
    const int4* sp = reinterpret_cast<const int4*>(&g_es[rp]);
    for (int it = 0; it < chunks; it++) {
        int4 qa = sp[4*it + 0];
        int4 qb = sp[4*it + 1];
        int4 qc = sp[4*it + 2];
        int4 qd = sp[4*it + 3];
        quad_acc(qa, lane, ax0, ay0);
        quad_acc(qb, lane, ax1, ay1);
        quad_acc(qc, lane, ax0, ay0);
        quad_acc(qd, lane, ax1, ay1);
    }
    float ax = ax0 + ax1, ay = ay0 + ay1;
    float dv = g_dinv[n];
    float2 bb = reinterpret_cast<const float2*>(b)[lane];
    float rx = tanhf(dv*ax + bb.x);
    float ry = tanhf(dv*ay + bb.y);
    g_h2[n*32 + lane] = __floats2half2_rn(rx, ry);
    if (POOL) {
        int g = batch[n];
        int base = g*DD + 2*lane;
        atomicMax(&g_gmax[base + 0], fkey(rx));
        atomicMax(&g_gmax[base + 1], fkey(ry));
        atomicAdd(&g_gsum[base + 0], rx);
        atomicAdd(&g_gsum[base + 1], ry);
        if (lane == 0) atomicAdd(&g_gcnt[g], 1.0f);
    }
}

// warp-per-graph output head
__global__ void k_out(const float* __restrict__ Wout, const float* __restrict__ bout,
                      float* __restrict__ out) {
    int g = (blockIdx.x * blockDim.x + threadIdx.x) >> 5;
    int lane = threadIdx.x & 31;
    if (g >= NG) return;
    float cnt = fmaxf(g_gcnt[g], 1.0f);
    float s = 0.0f;
    #pragma unroll
    for (int d = lane; d < DD; d += 32) {
        s += funkey(g_gmax[g*DD + d]) * Wout[d]
           + (g_gsum[g*DD + d] / cnt) * Wout[DD + d];
    }
    #pragma unroll
    for (int o = 16; o > 0; o >>= 1) s += __shfl_down_sync(0xFFFFFFFFu, s, o);
    if (lane == 0) out[g] = s + bout[0];
}

extern "C" void kernel_launch(void* const* d_in, const int* in_sizes, int n_in,
                              void* d_out, int out_size) {
    const float* x     = (const float*)d_in[0];
    const int*   eidx  = (const int*)  d_in[1];
    const int*   batch = (const int*)  d_in[2];
    const float* W0 = (const float*)d_in[3];  const float* b0 = (const float*)d_in[4];
    const float* W1 = (const float*)d_in[5];  const float* b1 = (const float*)d_in[6];
    const float* W2 = (const float*)d_in[7];  const float* b2 = (const float*)d_in[8];
    const float* W3 = (const float*)d_in[9];  const float* b3 = (const float*)d_in[10];
    const float* Wout = (const float*)d_in[11];
    const float* bout = (const float*)d_in[12];
    float* out = (float*)d_out;

    const int* src = eidx;
    const int* dst = eidx + NE;

    // ---- CSR build (rows padded to x16, blanket dummy fill) ----
    k_init <<<(EPAD/4 + 255) / 256, 256>>>();
    k_deg  <<<(NE/4 + 255) / 256, 256>>>((const int4*)dst);
    k_scan1<<<SCAN_BLKS, 256>>>();
    k_scan3<<<SCAN_BLKS, 256>>>();
    k_zx   <<<(NN*16 + 255) / 256, 256>>>(x);
    k_fill <<<(NE/8 + 255) / 256, 256>>>((const int4*)src, (const int4*)dst);

    const int g9_blocks = (NN * 16 + 255) / 256;   // 3125
    const int gw_blocks = (NN * 32 + 255) / 256;   // 6250 (warp per node)
    const int gm_blocks = (NN + GMN - 1) / GMN;    // 782

    // layer 0
    k_gather9<<<g9_blocks, 256>>>();
    k_gemm0f <<<(NN + 7) / 8, 256>>>(W0, b0);
    // layers 1-3
    k_gemm64  <<<gm_blocks, 256>>>(W1);
    k_gather64<false><<<gw_blocks, 256>>>(b1, batch);
    k_gemm64  <<<gm_blocks, 256>>>(W2);
    k_gather64<false><<<gw_blocks, 256>>>(b2, batch);
    k_gemm64  <<<gm_blocks, 256>>>(W3);
    k_gather64<true> <<<gw_blocks, 256>>>(b3, batch);

    k_out<<<(NG*32 + 255) / 256, 256>>>(Wout, bout, out);
}

// round 13
// speedup vs baseline: 1.0072x; 1.0072x over previous
#include <cuda_runtime.h>
#include <cuda_fp16.h>
#include <mma.h>

using namespace nvcuda;

#define NN 50000
#define NE 800000
#define NG 1024
#define DIN 9
#define DD 64
#define SCAN_BLKS ((NN + 255) / 256)   // 196
#define GMN 64                          // nodes per gemm64 block
#define EPAD (NE + 4*NN)                // padded edge array size (rows padded to x4)

// ---- scratch (static device globals) ----
__device__ __half2  g_h2 [NN*32];        // activations (post-tanh), fp16
__device__ __half2  g_z2 [(NN+1)*32];    // z = dinv * (h @ W), fp16; row NN = 0
__device__ float    g_zx [(NN+1)*16];    // dinv * x, padded to 16; row NN = 0
__device__ float    g_aggx[NN*DIN];      // layer-0 aggregate
__device__ int      g_degi[NN];          // in-degree (no self loop)
__device__ float    g_dinv[NN];
__device__ int      g_rp  [NN];          // padded CSR row start (4-aligned)
__device__ int      g_cur [NN];          // fill cursor (pre-seeded with rp)
__device__ int      g_es  [EPAD];        // src indices, padded rows -> NN
__device__ int      g_bsum[256];
__device__ unsigned g_gmax[NG*DD];
__device__ float    g_gsum[NG*DD];
__device__ float    g_gcnt[NG];

__device__ __forceinline__ unsigned fkey(float f) {
    unsigned b = __float_as_uint(f);
    return (b & 0x80000000u) ? ~b : (b | 0x80000000u);
}
__device__ __forceinline__ float funkey(unsigned k) {
    unsigned b = (k & 0x80000000u) ? (k & 0x7FFFFFFFu) : ~k;
    return __uint_as_float(b);
}

__global__ void k_init() {
    int i = blockIdx.x * blockDim.x + threadIdx.x;
    if (i < NN) g_degi[i] = 0;
    if (i < NG*DD) { g_gmax[i] = 0u; g_gsum[i] = 0.0f; }
    if (i < NG) g_gcnt[i] = 0.0f;
    if (i < 32) g_z2[NN*32 + i] = __float2half2_rn(0.0f);   // dummy z row
    if (i < 16) g_zx[NN*16 + i] = 0.0f;                     // dummy zx row
}

__global__ void k_deg(const int4* __restrict__ dst4) {
    int e = blockIdx.x * blockDim.x + threadIdx.x;
    if (e >= NE/4) return;
    int4 d = dst4[e];
    atomicAdd(&g_degi[d.x], 1);
    atomicAdd(&g_degi[d.y], 1);
    atomicAdd(&g_degi[d.z], 1);
    atomicAdd(&g_degi[d.w], 1);
}

// shuffle scan of PADDED degree -> rp (exclusive), block sums
__global__ void k_scan1() {
    __shared__ int wsum[8], wpre[8];
    int t = threadIdx.x, i = blockIdx.x * 256 + t;
    int lane = t & 31, w = t >> 5;
    int v = (i < NN) ? ((g_degi[i] + 3) & ~3) : 0;
    int s = v;
    #pragma unroll
    for (int off = 1; off < 32; off <<= 1) {
        int u = __shfl_up_sync(0xFFFFFFFFu, s, off);
        if (lane >= off) s += u;
    }
    if (lane == 31) wsum[w] = s;
    __syncthreads();
    if (t == 0) {
        int a = 0;
        #pragma unroll
        for (int j = 0; j < 8; j++) { wpre[j] = a; a += wsum[j]; }
    }
    __syncthreads();
    int incl = s + wpre[w];
    if (i < NN) g_rp[i] = incl - v;
    if (t == 255) g_bsum[blockIdx.x] = incl;
}

// re-scan bsum + apply; cursor=rp, dinv, pad-slot fill (zx split out)
__global__ void k_scan3() {
    __shared__ int wsum[8], wpre[8], allincl[256];
    int t = threadIdx.x;
    int lane = t & 31, w = t >> 5;
    int v = (t < SCAN_BLKS) ? g_bsum[t] : 0;
    int s = v;
    #pragma unroll
    for (int off = 1; off < 32; off <<= 1) {
        int u = __shfl_up_sync(0xFFFFFFFFu, s, off);
        if (lane >= off) s += u;
    }
    if (lane == 31) wsum[w] = s;
    __syncthreads();
    if (t == 0) {
        int a = 0;
        #pragma unroll
        for (int j = 0; j < 8; j++) { wpre[j] = a; a += wsum[j]; }
    }
    __syncthreads();
    allincl[t] = s + wpre[w];
    __syncthreads();
    int boff = (blockIdx.x > 0) ? allincl[blockIdx.x - 1] : 0;
    int i = blockIdx.x * 256 + t;
    if (i < NN) {
        int rp = g_rp[i] + boff;
        g_rp[i] = rp;
        g_cur[i] = rp;
        int dg = g_degi[i];
        g_dinv[i] = rsqrtf(1.0f + (float)dg);
        int pdg = (dg + 3) & ~3;
        for (int p = dg; p < pdg; p++) g_es[rp + p] = NN;   // pad -> dummy node
    }
}

// coalesced zx = dinv * x (padded to 16 floats/row)
__global__ void k_zx(const float* __restrict__ x) {
    int t = blockIdx.x * blockDim.x + threadIdx.x;
    if (t >= NN*16) return;
    int n = t >> 4, k = t & 15;
    float v = (k < DIN) ? g_dinv[n] * x[n*DIN + k] : 0.0f;
    g_zx[t] = v;
}

// 2 int4s per thread: 8 independent atomic->store chains; cur pre-seeded with rp
__global__ void k_fill(const int4* __restrict__ src4, const int4* __restrict__ dst4) {
    int e = blockIdx.x * blockDim.x + threadIdx.x;
    if (e >= NE/8) return;
    int4 s0 = src4[2*e], d0 = dst4[2*e];
    int4 s1 = src4[2*e+1], d1 = dst4[2*e+1];
    g_es[atomicAdd(&g_cur[d0.x], 1)] = s0.x;
    g_es[atomicAdd(&g_cur[d0.y], 1)] = s0.y;
    g_es[atomicAdd(&g_cur[d0.z], 1)] = s0.z;
    g_es[atomicAdd(&g_cur[d0.w], 1)] = s0.w;
    g_es[atomicAdd(&g_cur[d1.x], 1)] = s1.x;
    g_es[atomicAdd(&g_cur[d1.y], 1)] = s1.y;
    g_es[atomicAdd(&g_cur[d1.z], 1)] = s1.z;
    g_es[atomicAdd(&g_cur[d1.w], 1)] = s1.w;
}

// layer-0: aggx[d] = dinv[d] * (zx[d] + sum zx[s]); 16 lanes/node, padded rows
__global__ void k_gather9() {
    int t = blockIdx.x * blockDim.x + threadIdx.x;
    int n = t >> 4, c = t & 15;
    if (n >= NN) return;
    int rp = g_rp[n];
    int quads = ((g_degi[n] + 3) & ~3) >> 2;
    float a0 = __ldg(&g_zx[n*16 + c]), a1 = 0.0f;
    const int4* sp = reinterpret_cast<const int4*>(&g_es[rp]);
    int it = 0;
    for (; it + 2 <= quads; it += 2) {
        int4 s0 = sp[it], s1 = sp[it + 1];
        a0 += __ldg(&g_zx[s0.x*16 + c]);
        a1 += __ldg(&g_zx[s0.y*16 + c]);
        a0 += __ldg(&g_zx[s0.z*16 + c]);
        a1 += __ldg(&g_zx[s0.w*16 + c]);
        a0 += __ldg(&g_zx[s1.x*16 + c]);
        a1 += __ldg(&g_zx[s1.y*16 + c]);
        a0 += __ldg(&g_zx[s1.z*16 + c]);
        a1 += __ldg(&g_zx[s1.w*16 + c]);
    }
    if (it < quads) {
        int4 s0 = sp[it];
        a0 += __ldg(&g_zx[s0.x*16 + c]);
        a1 += __ldg(&g_zx[s0.y*16 + c]);
        a0 += __ldg(&g_zx[s0.z*16 + c]);
        a1 += __ldg(&g_zx[s0.w*16 + c]);
    }
    if (c < DIN) g_aggx[n*DIN + c] = g_dinv[n] * (a0 + a1);
}

// h0 = tanh(aggx @ W0 + b0) -> fp16; 8 nodes/block, lane computes 2 cols
__global__ void k_gemm0f(const float* __restrict__ W, const float* __restrict__ b) {
    __shared__ float Ws[DIN*DD];
    __shared__ float axs[8][DIN];
    int tid = threadIdx.x;
    for (int i = tid; i < DIN*DD; i += 256) Ws[i] = W[i];
    int nb = blockIdx.x * 8;
    if (tid < 8*DIN) {
        int r = tid / DIN, k = tid % DIN, n = nb + r;
        axs[r][k] = (n < NN) ? g_aggx[n*DIN + k] : 0.0f;
    }
    __syncthreads();
    int r = tid >> 5, l = tid & 31;
    int n = nb + r;
    if (n >= NN) return;
    int c0 = 2*l, c1 = 2*l + 1;
    float s0 = b[c0], s1 = b[c1];
    #pragma unroll
    for (int k = 0; k < DIN; k++) {
        float a = axs[r][k];
        s0 += a * Ws[k*DD + c0];
        s1 += a * Ws[k*DD + c1];
    }
    g_h2[n*32 + l] = __floats2half2_rn(tanhf(s0), tanhf(s1));
}

// z = dinv * (h @ W) via tensor cores: fp16 in, fp32 acc, fp16 out.
#define HP 72   // Hs/Wsh pitch in halfs (mult of 8)
__global__ void k_gemm64(const float* __restrict__ W) {
    __shared__ __half Hs [GMN][HP];
    __shared__ __half Wsh[DD ][HP];
    __shared__ float  stage[8][16][20];
    int tid = threadIdx.x;
    int wid = tid >> 5, lane = tid & 31;
    int nb = blockIdx.x * GMN;

    #pragma unroll
    for (int i = 0; i < 4; i++) {
        int idx = tid + i*256;
        float4 f = reinterpret_cast<const float4*>(W)[idx];
        int r = idx >> 4, c0 = (idx & 15) * 4;
        __half2 p0 = __floats2half2_rn(f.x, f.y);
        __half2 p1 = __floats2half2_rn(f.z, f.w);
        *reinterpret_cast<__half2*>(&Wsh[r][c0])     = p0;
        *reinterpret_cast<__half2*>(&Wsh[r][c0 + 2]) = p1;
    }
    #pragma unroll
    for (int i = 0; i < 2; i++) {
        int idx = tid + i*256;
        int n = idx >> 3, q = idx & 7;
        int gn = nb + n;
        uint4 v = make_uint4(0u, 0u, 0u, 0u);
        if (gn < NN) v = reinterpret_cast<const uint4*>(g_h2)[gn*8 + q];
        *reinterpret_cast<uint4*>(&Hs[n][q*8]) = v;
    }
    __syncthreads();

    wmma::fragment<wmma::matrix_a, 16, 16, 16, __half, wmma::row_major> fa;
    wmma::fragment<wmma::matrix_b, 16, 16, 16, __half, wmma::row_major> fb;

    #pragma unroll
    for (int tt = 0; tt < 2; tt++) {
        int t = wid + tt*8;
        int tr = t >> 2, tc = t & 3;
        wmma::fragment<wmma::accumulator, 16, 16, 16, float> fc;
        wmma::fill_fragment(fc, 0.0f);
        #pragma unroll
        for (int k0 = 0; k0 < 4; k0++) {
            wmma::load_matrix_sync(fa, &Hs[tr*16][k0*16], HP);
            wmma::load_matrix_sync(fb, &Wsh[k0*16][tc*16], HP);
            wmma::mma_sync(fc, fa, fb, fc);
        }
        wmma::store_matrix_sync(&stage[wid][0][0], fc, 20, wmma::mem_row_major);
        __syncwarp();
        #pragma unroll
        for (int e = 0; e < 4; e++) {
            int idx = lane + e*32;
            int r = idx >> 3, c2 = idx & 7;
            int gn = nb + tr*16 + r;
            if (gn < NN) {
                float dv = g_dinv[gn];
                float f0 = stage[wid][r][c2*2];
                float f1 = stage[wid][r][c2*2 + 1];
                g_z2[gn*32 + tc*8 + c2] = __floats2half2_rn(dv*f0, dv*f1);
            }
        }
        __syncwarp();
    }
}

// gather: fp16 quad-tree accumulate, fp32 flush per quad; warp-per-node (R10 best)
template <bool POOL>
__global__ void k_gather64(const float* __restrict__ b, const int* __restrict__ batch) {
    int n = (blockIdx.x * blockDim.x + threadIdx.x) >> 5;
    int lane = threadIdx.x & 31;
    if (n >= NN) return;
    int rp = g_rp[n];
    int quads = ((g_degi[n] + 3) & ~3) >> 2;
    float2 self = __half22float2(__ldg(&g_z2[n*32 + lane]));
    float ax = self.x, ay = self.y;
    const int4* sp = reinterpret_cast<const int4*>(&g_es[rp]);
    int it = 0;
    for (; it + 2 <= quads; it += 2) {      // 8 edges in flight
        int4 q0 = sp[it], q1 = sp[it + 1];
        __half2 h0 = __ldg(&g_z2[q0.x*32 + lane]);
        __half2 h1 = __ldg(&g_z2[q0.y*32 + lane]);
        __half2 h2 = __ldg(&g_z2[q0.z*32 + lane]);
        __half2 h3 = __ldg(&g_z2[q0.w*32 + lane]);
        __half2 h4 = __ldg(&g_z2[q1.x*32 + lane]);
        __half2 h5 = __ldg(&g_z2[q1.y*32 + lane]);
        __half2 h6 = __ldg(&g_z2[q1.z*32 + lane]);
        __half2 h7 = __ldg(&g_z2[q1.w*32 + lane]);
        __half2 sA = __hadd2(__hadd2(h0, h1), __hadd2(h2, h3));   // depth-2 tree
        __half2 sB = __hadd2(__hadd2(h4, h5), __hadd2(h6, h7));
        float2 fA = __half22float2(sA);
        float2 fB = __half22float2(sB);
        ax += fA.x + fB.x;
        ay += fA.y + fB.y;
    }
    if (it < quads) {
        int4 q0 = sp[it];
        __half2 h0 = __ldg(&g_z2[q0.x*32 + lane]);
        __half2 h1 = __ldg(&g_z2[q0.y*32 + lane]);
        __half2 h2 = __ldg(&g_z2[q0.z*32 + lane]);
        __half2 h3 = __ldg(&g_z2[q0.w*32 + lane]);
        __half2 sA = __hadd2(__hadd2(h0, h1), __hadd2(h2, h3));
        float2 fA = __half22float2(sA);
        ax += fA.x;
        ay += fA.y;
    }
    float dv = g_dinv[n];
    float2 bb = reinterpret_cast<const float2*>(b)[lane];
    float rx = tanhf(dv*ax + bb.x);
    float ry = tanhf(dv*ay + bb.y);
    g_h2[n*32 + lane] = __floats2half2_rn(rx, ry);
    if (POOL) {
        int g = batch[n];
        int base = g*DD + 2*lane;
        atomicMax(&g_gmax[base + 0], fkey(rx));
        atomicMax(&g_gmax[base + 1], fkey(ry));
        atomicAdd(&g_gsum[base + 0], rx);
        atomicAdd(&g_gsum[base + 1], ry);
        if (lane == 0) atomicAdd(&g_gcnt[g], 1.0f);
    }
}

// warp-per-graph output head
__global__ void k_out(const float* __restrict__ Wout, const float* __restrict__ bout,
                      float* __restrict__ out) {
    int g = (blockIdx.x * blockDim.x + threadIdx.x) >> 5;
    int lane = threadIdx.x & 31;
    if (g >= NG) return;
    float cnt = fmaxf(g_gcnt[g], 1.0f);
    float s = 0.0f;
    #pragma unroll
    for (int d = lane; d < DD; d += 32) {
        s += funkey(g_gmax[g*DD + d]) * Wout[d]
           + (g_gsum[g*DD + d] / cnt) * Wout[DD + d];
    }
    #pragma unroll
    for (int o = 16; o > 0; o >>= 1) s += __shfl_down_sync(0xFFFFFFFFu, s, o);
    if (lane == 0) out[g] = s + bout[0];
}

extern "C" void kernel_launch(void* const* d_in, const int* in_sizes, int n_in,
                              void* d_out, int out_size) {
    const float* x     = (const float*)d_in[0];
    const int*   eidx  = (const int*)  d_in[1];
    const int*   batch = (const int*)  d_in[2];
    const float* W0 = (const float*)d_in[3];  const float* b0 = (const float*)d_in[4];
    const float* W1 = (const float*)d_in[5];  const float* b1 = (const float*)d_in[6];
    const float* W2 = (const float*)d_in[7];  const float* b2 = (const float*)d_in[8];
    const float* W3 = (const float*)d_in[9];  const float* b3 = (const float*)d_in[10];
    const float* Wout = (const float*)d_in[11];
    const float* bout = (const float*)d_in[12];
    float* out = (float*)d_out;

    const int* src = eidx;
    const int* dst = eidx + NE;

    // ---- CSR build (rows padded to x4, index-only edges) ----
    k_init <<<(NG*DD + 255) / 256, 256>>>();
    k_deg  <<<(NE/4 + 255) / 256, 256>>>((const int4*)dst);
    k_scan1<<<SCAN_BLKS, 256>>>();
    k_scan3<<<SCAN_BLKS, 256>>>();
    k_zx   <<<(NN*16 + 255) / 256, 256>>>(x);
    k_fill <<<(NE/8 + 255) / 256, 256>>>((const int4*)src, (const int4*)dst);

    const int g9_blocks = (NN * 16 + 255) / 256;   // 3125
    const int gw_blocks = (NN * 32 + 255) / 256;   // 6250 (warp per node)
    const int gm_blocks = (NN + GMN - 1) / GMN;    // 782

    // layer 0
    k_gather9<<<g9_blocks, 256>>>();
    k_gemm0f <<<(NN + 7) / 8, 256>>>(W0, b0);
    // layers 1-3
    k_gemm64  <<<gm_blocks, 256>>>(W1);
    k_gather64<false><<<gw_blocks, 256>>>(b1, batch);
    k_gemm64  <<<gm_blocks, 256>>>(W2);
    k_gather64<false><<<gw_blocks, 256>>>(b2, batch);
    k_gemm64  <<<gm_blocks, 256>>>(W3);
    k_gather64<true> <<<gw_blocks, 256>>>(b3, batch);

    k_out<<<(NG*32 + 255) / 256, 256>>>(Wout, bout, out);
}

// round 14
// speedup vs baseline: 1.0161x; 1.0088x over previous
#include <cuda_runtime.h>
#include <cuda_fp16.h>
#include <mma.h>

using namespace nvcuda;

#define NN 50000
#define NE 800000
#define NG 1024
#define DIN 9
#define DD 64
#define SCAN_BLKS ((NN + 255) / 256)   // 196
#define GMN 64                          // nodes per gemm64 block
#define EPAD (NE + 4*NN)                // padded edge array size (rows padded to x4)

// ---- scratch (static device globals) ----
__device__ __half2  g_h2 [NN*32];        // activations (post-tanh), fp16
__device__ __half2  g_z2 [(NN+1)*32];    // z = dinv * (h @ W), fp16; row NN = 0
__device__ __half   g_zxh[(NN+1)*16];    // dinv * x, fp16, padded to 16; row NN = 0
__device__ float    g_aggx[NN*DIN];      // layer-0 aggregate
__device__ int      g_degi[NN];          // in-degree (no self loop)
__device__ float    g_dinv[NN];
__device__ int      g_rp  [NN];          // padded CSR row start (4-aligned)
__device__ int      g_cur [NN];          // fill cursor (pre-seeded with rp)
__device__ int      g_es  [EPAD];        // src indices, padded rows -> NN
__device__ int      g_flag[256];         // lookback: block total + 1 (0 = not ready)
__device__ unsigned g_gmax[NG*DD];
__device__ float    g_gsum[NG*DD];
__device__ float    g_gcnt[NG];

__device__ __forceinline__ unsigned fkey(float f) {
    unsigned b = __float_as_uint(f);
    return (b & 0x80000000u) ? ~b : (b | 0x80000000u);
}
__device__ __forceinline__ float funkey(unsigned k) {
    unsigned b = (k & 0x80000000u) ? (k & 0x7FFFFFFFu) : ~k;
    return __uint_as_float(b);
}

__global__ void k_init() {
    int i = blockIdx.x * blockDim.x + threadIdx.x;
    if (i < NN) g_degi[i] = 0;
    if (i < NG*DD) { g_gmax[i] = 0u; g_gsum[i] = 0.0f; }
    if (i < NG) g_gcnt[i] = 0.0f;
    if (i < 256) g_flag[i] = 0;
    if (i < 32) g_z2[NN*32 + i] = __float2half2_rn(0.0f);   // dummy z row
    if (i < 16) g_zxh[NN*16 + i] = __float2half(0.0f);      // dummy zx row
}

__global__ void k_deg(const int4* __restrict__ dst4) {
    int e = blockIdx.x * blockDim.x + threadIdx.x;
    if (e >= NE/4) return;
    int4 d = dst4[e];
    atomicAdd(&g_degi[d.x], 1);
    atomicAdd(&g_degi[d.y], 1);
    atomicAdd(&g_degi[d.z], 1);
    atomicAdd(&g_degi[d.w], 1);
}

// single-kernel exclusive scan of padded degree via publish-then-lookback;
// also: cursor=rp, dinv, zx(fp16) = dinv*x, pad-slot fill
__global__ void k_scan(const float* __restrict__ x) {
    __shared__ int wsum[8], wpre[8];
    __shared__ int boff_sh, total_sh;
    int t = threadIdx.x, b = blockIdx.x;
    int lane = t & 31, w = t >> 5;
    int i = b * 256 + t;
    int dg = (i < NN) ? g_degi[i] : 0;
    int v = (dg + 3) & ~3;

    // warp inclusive scan
    int s = v;
    #pragma unroll
    for (int off = 1; off < 32; off <<= 1) {
        int u = __shfl_up_sync(0xFFFFFFFFu, s, off);
        if (lane >= off) s += u;
    }
    if (lane == 31) wsum[w] = s;
    __syncthreads();
    if (t == 0) {
        int a = 0;
        #pragma unroll
        for (int j = 0; j < 8; j++) { wpre[j] = a; a += wsum[j]; }
        total_sh = a;
        // publish own total FIRST (single-word publish: total+1, 0 = not ready)
        atomicExch(&g_flag[b], a + 1);
    }
    __syncthreads();

    // warp 0: lookback over predecessors (each publishes independently)
    if (w == 0) {
        int sum = 0;
        for (int j = lane; j < b; j += 32) {
            int f;
            do { f = atomicAdd(&g_flag[j], 0); } while (f == 0);
            sum += f - 1;
        }
        #pragma unroll
        for (int o = 16; o > 0; o >>= 1) sum += __shfl_down_sync(0xFFFFFFFFu, sum, o);
        if (lane == 0) boff_sh = sum;
    }
    __syncthreads();
    int boff = boff_sh;

    if (i < NN) {
        int rp = (s + wpre[w]) - v + boff;   // exclusive prefix
        g_rp[i] = rp;
        g_cur[i] = rp;
        float dv = rsqrtf(1.0f + (float)dg);
        g_dinv[i] = dv;
        #pragma unroll
        for (int k = 0; k < DIN; k++) g_zxh[i*16 + k] = __float2half(dv * x[i*DIN + k]);
        #pragma unroll
        for (int k = DIN; k < 16; k++) g_zxh[i*16 + k] = __float2half(0.0f);
        int pdg = (dg + 3) & ~3;
        for (int p = dg; p < pdg; p++) g_es[rp + p] = NN;   // pad -> dummy node
    }
}

// 2 int4s per thread: 8 independent atomic->store chains; cur pre-seeded with rp
__global__ void k_fill(const int4* __restrict__ src4, const int4* __restrict__ dst4) {
    int e = blockIdx.x * blockDim.x + threadIdx.x;
    if (e >= NE/8) return;
    int4 s0 = src4[2*e], d0 = dst4[2*e];
    int4 s1 = src4[2*e+1], d1 = dst4[2*e+1];
    g_es[atomicAdd(&g_cur[d0.x], 1)] = s0.x;
    g_es[atomicAdd(&g_cur[d0.y], 1)] = s0.y;
    g_es[atomicAdd(&g_cur[d0.z], 1)] = s0.z;
    g_es[atomicAdd(&g_cur[d0.w], 1)] = s0.w;
    g_es[atomicAdd(&g_cur[d1.x], 1)] = s1.x;
    g_es[atomicAdd(&g_cur[d1.y], 1)] = s1.y;
    g_es[atomicAdd(&g_cur[d1.z], 1)] = s1.z;
    g_es[atomicAdd(&g_cur[d1.w], 1)] = s1.w;
}

// layer-0: aggx[d] = dinv[d] * (zx[d] + sum zx[s]); 16 lanes/node, fp16 zx rows
__global__ void k_gather9() {
    int t = blockIdx.x * blockDim.x + threadIdx.x;
    int n = t >> 4, c = t & 15;
    if (n >= NN) return;
    int rp = g_rp[n];
    int quads = ((g_degi[n] + 3) & ~3) >> 2;
    float a0 = __half2float(g_zxh[n*16 + c]), a1 = 0.0f;
    const int4* sp = reinterpret_cast<const int4*>(&g_es[rp]);
    int it = 0;
    for (; it + 2 <= quads; it += 2) {
        int4 s0 = sp[it], s1 = sp[it + 1];
        a0 += __half2float(g_zxh[s0.x*16 + c]);
        a1 += __half2float(g_zxh[s0.y*16 + c]);
        a0 += __half2float(g_zxh[s0.z*16 + c]);
        a1 += __half2float(g_zxh[s0.w*16 + c]);
        a0 += __half2float(g_zxh[s1.x*16 + c]);
        a1 += __half2float(g_zxh[s1.y*16 + c]);
        a0 += __half2float(g_zxh[s1.z*16 + c]);
        a1 += __half2float(g_zxh[s1.w*16 + c]);
    }
    if (it < quads) {
        int4 s0 = sp[it];
        a0 += __half2float(g_zxh[s0.x*16 + c]);
        a1 += __half2float(g_zxh[s0.y*16 + c]);
        a0 += __half2float(g_zxh[s0.z*16 + c]);
        a1 += __half2float(g_zxh[s0.w*16 + c]);
    }
    if (c < DIN) g_aggx[n*DIN + c] = g_dinv[n] * (a0 + a1);
}

// h0 = tanh(aggx @ W0 + b0) -> fp16; 8 nodes/block, lane computes 2 cols
__global__ void k_gemm0f(const float* __restrict__ W, const float* __restrict__ b) {
    __shared__ float Ws[DIN*DD];
    __shared__ float axs[8][DIN];
    int tid = threadIdx.x;
    for (int i = tid; i < DIN*DD; i += 256) Ws[i] = W[i];
    int nb = blockIdx.x * 8;
    if (tid < 8*DIN) {
        int r = tid / DIN, k = tid % DIN, n = nb + r;
        axs[r][k] = (n < NN) ? g_aggx[n*DIN + k] : 0.0f;
    }
    __syncthreads();
    int r = tid >> 5, l = tid & 31;
    int n = nb + r;
    if (n >= NN) return;
    int c0 = 2*l, c1 = 2*l + 1;
    float s0 = b[c0], s1 = b[c1];
    #pragma unroll
    for (int k = 0; k < DIN; k++) {
        float a = axs[r][k];
        s0 += a * Ws[k*DD + c0];
        s1 += a * Ws[k*DD + c1];
    }
    g_h2[n*32 + l] = __floats2half2_rn(tanhf(s0), tanhf(s1));
}

// z = dinv * (h @ W) via tensor cores: fp16 in, fp32 acc, fp16 out.
#define HP 72   // Hs/Wsh pitch in halfs (mult of 8)
__global__ void k_gemm64(const float* __restrict__ W) {
    __shared__ __half Hs [GMN][HP];
    __shared__ __half Wsh[DD ][HP];
    __shared__ float  stage[8][16][20];
    int tid = threadIdx.x;
    int wid = tid >> 5, lane = tid & 31;
    int nb = blockIdx.x * GMN;

    #pragma unroll
    for (int i = 0; i < 4; i++) {
        int idx = tid + i*256;
        float4 f = reinterpret_cast<const float4*>(W)[idx];
        int r = idx >> 4, c0 = (idx & 15) * 4;
        __half2 p0 = __floats2half2_rn(f.x, f.y);
        __half2 p1 = __floats2half2_rn(f.z, f.w);
        *reinterpret_cast<__half2*>(&Wsh[r][c0])     = p0;
        *reinterpret_cast<__half2*>(&Wsh[r][c0 + 2]) = p1;
    }
    #pragma unroll
    for (int i = 0; i < 2; i++) {
        int idx = tid + i*256;
        int n = idx >> 3, q = idx & 7;
        int gn = nb + n;
        uint4 v = make_uint4(0u, 0u, 0u, 0u);
        if (gn < NN) v = reinterpret_cast<const uint4*>(g_h2)[gn*8 + q];
        *reinterpret_cast<uint4*>(&Hs[n][q*8]) = v;
    }
    __syncthreads();

    wmma::fragment<wmma::matrix_a, 16, 16, 16, __half, wmma::row_major> fa;
    wmma::fragment<wmma::matrix_b, 16, 16, 16, __half, wmma::row_major> fb;

    #pragma unroll
    for (int tt = 0; tt < 2; tt++) {
        int t = wid + tt*8;
        int tr = t >> 2, tc = t & 3;
        wmma::fragment<wmma::accumulator, 16, 16, 16, float> fc;
        wmma::fill_fragment(fc, 0.0f);
        #pragma unroll
        for (int k0 = 0; k0 < 4; k0++) {
            wmma::load_matrix_sync(fa, &Hs[tr*16][k0*16], HP);
            wmma::load_matrix_sync(fb, &Wsh[k0*16][tc*16], HP);
            wmma::mma_sync(fc, fa, fb, fc);
        }
        wmma::store_matrix_sync(&stage[wid][0][0], fc, 20, wmma::mem_row_major);
        __syncwarp();
        #pragma unroll
        for (int e = 0; e < 4; e++) {
            int idx = lane + e*32;
            int r = idx >> 3, c2 = idx & 7;
            int gn = nb + tr*16 + r;
            if (gn < NN) {
                float dv = g_dinv[gn];
                float f0 = stage[wid][r][c2*2];
                float f1 = stage[wid][r][c2*2 + 1];
                g_z2[gn*32 + tc*8 + c2] = __floats2half2_rn(dv*f0, dv*f1);
            }
        }
        __syncwarp();
    }
}

// gather: fp16 quad-tree accumulate, fp32 flush per quad; warp-per-node (R10 best)
template <bool POOL>
__global__ void k_gather64(const float* __restrict__ b, const int* __restrict__ batch) {
    int n = (blockIdx.x * blockDim.x + threadIdx.x) >> 5;
    int lane = threadIdx.x & 31;
    if (n >= NN) return;
    int rp = g_rp[n];
    int quads = ((g_degi[n] + 3) & ~3) >> 2;
    float2 self = __half22float2(g_z2[n*32 + lane]);
    float ax = self.x, ay = self.y;
    const int4* sp = reinterpret_cast<const int4*>(&g_es[rp]);
    int it = 0;
    for (; it + 2 <= quads; it += 2) {      // 8 edges in flight
        int4 q0 = sp[it], q1 = sp[it + 1];
        __half2 h0 = g_z2[q0.x*32 + lane];
        __half2 h1 = g_z2[q0.y*32 + lane];
        __half2 h2 = g_z2[q0.z*32 + lane];
        __half2 h3 = g_z2[q0.w*32 + lane];
        __half2 h4 = g_z2[q1.x*32 + lane];
        __half2 h5 = g_z2[q1.y*32 + lane];
        __half2 h6 = g_z2[q1.z*32 + lane];
        __half2 h7 = g_z2[q1.w*32 + lane];
        __half2 sA = __hadd2(__hadd2(h0, h1), __hadd2(h2, h3));   // depth-2 tree
        __half2 sB = __hadd2(__hadd2(h4, h5), __hadd2(h6, h7));
        float2 fA = __half22float2(sA);
        float2 fB = __half22float2(sB);
        ax += fA.x + fB.x;
        ay += fA.y + fB.y;
    }
    if (it < quads) {
        int4 q0 = sp[it];
        __half2 h0 = g_z2[q0.x*32 + lane];
        __half2 h1 = g_z2[q0.y*32 + lane];
        __half2 h2 = g_z2[q0.z*32 + lane];
        __half2 h3 = g_z2[q0.w*32 + lane];
        __half2 sA = __hadd2(__hadd2(h0, h1), __hadd2(h2, h3));
        float2 fA = __half22float2(sA);
        ax += fA.x;
        ay += fA.y;
    }
    float dv = g_dinv[n];
    float2 bb = reinterpret_cast<const float2*>(b)[lane];
    float rx = tanhf(dv*ax + bb.x);
    float ry = tanhf(dv*ay + bb.y);
    g_h2[n*32 + lane] = __floats2half2_rn(rx, ry);
    if (POOL) {
        int g = batch[n];
        int base = g*DD + 2*lane;
        atomicMax(&g_gmax[base + 0], fkey(rx));
        atomicMax(&g_gmax[base + 1], fkey(ry));
        atomicAdd(&g_gsum[base + 0], rx);
        atomicAdd(&g_gsum[base + 1], ry);
        if (lane == 0) atomicAdd(&g_gcnt[g], 1.0f);
    }
}

// warp-per-graph output head
__global__ void k_out(const float* __restrict__ Wout, const float* __restrict__ bout,
                      float* __restrict__ out) {
    int g = (blockIdx.x * blockDim.x + threadIdx.x) >> 5;
    int lane = threadIdx.x & 31;
    if (g >= NG) return;
    float cnt = fmaxf(g_gcnt[g], 1.0f);
    float s = 0.0f;
    #pragma unroll
    for (int d = lane; d < DD; d += 32) {
        s += funkey(g_gmax[g*DD + d]) * Wout[d]
           + (g_gsum[g*DD + d] / cnt) * Wout[DD + d];
    }
    #pragma unroll
    for (int o = 16; o > 0; o >>= 1) s += __shfl_down_sync(0xFFFFFFFFu, s, o);
    if (lane == 0) out[g] = s + bout[0];
}

extern "C" void kernel_launch(void* const* d_in, const int* in_sizes, int n_in,
                              void* d_out, int out_size) {
    const float* x     = (const float*)d_in[0];
    const int*   eidx  = (const int*)  d_in[1];
    const int*   batch = (const int*)  d_in[2];
    const float* W0 = (const float*)d_in[3];  const float* b0 = (const float*)d_in[4];
    const float* W1 = (const float*)d_in[5];  const float* b1 = (const float*)d_in[6];
    const float* W2 = (const float*)d_in[7];  const float* b2 = (const float*)d_in[8];
    const float* W3 = (const float*)d_in[9];  const float* b3 = (const float*)d_in[10];
    const float* Wout = (const float*)d_in[11];
    const float* bout = (const float*)d_in[12];
    float* out = (float*)d_out;

    const int* src = eidx;
    const int* dst = eidx + NE;

    // ---- CSR build (rows padded to x4, index-only edges) ----
    k_init <<<(NG*DD + 255) / 256, 256>>>();
    k_deg  <<<(NE/4 + 255) / 256, 256>>>((const int4*)dst);
    k_scan <<<SCAN_BLKS, 256>>>(x);
    k_fill <<<(NE/8 + 255) / 256, 256>>>((const int4*)src, (const int4*)dst);

    const int g9_blocks = (NN * 16 + 255) / 256;   // 3125
    const int gw_blocks = (NN * 32 + 255) / 256;   // 6250 (warp per node)
    const int gm_blocks = (NN + GMN - 1) / GMN;    // 782

    // layer 0
    k_gather9<<<g9_blocks, 256>>>();
    k_gemm0f <<<(NN + 7) / 8, 256>>>(W0, b0);
    // layers 1-3
    k_gemm64  <<<gm_blocks, 256>>>(W1);
    k_gather64<false><<<gw_blocks, 256>>>(b1, batch);
    k_gemm64  <<<gm_blocks, 256>>>(W2);
    k_gather64<false><<<gw_blocks, 256>>>(b2, batch);
    k_gemm64  <<<gm_blocks, 256>>>(W3);
    k_gather64<true> <<<gw_blocks, 256>>>(b3, batch);

    k_out<<<(NG*32 + 255) / 256, 256>>>(Wout, bout, out);
}